// round 6
// baseline (speedup 1.0000x reference)
#include <cuda_runtime.h>
#include <cuda_bf16.h>
#include <math.h>

#define N_NODES 100000
#define N_EDGES 1600000
#define D 64
#define EPSV 1e-7f
#define SCAN_BLK 1024
#define N_SCAN_BLKS ((N_NODES + SCAN_BLK - 1) / SCAN_BLK)   // 98

// Scratch (device globals; allocation is forbidden)
__device__ float g_s1[N_NODES * D];
__device__ float g_s2[N_NODES * D];
__device__ int   g_cnt[N_NODES];
__device__ int   g_rowptr[N_NODES + 1];
__device__ int   g_cur[N_NODES];
__device__ int   g_bsum[N_SCAN_BLKS];
__device__ int   g_csr[N_EDGES];
__device__ float g_wt[448 * 64];     // permuted weights (k-pair interleaved)

// ---------------------------------------------------------------------------
// K0: permute weights (lane-coalesced k-pair interleave) + zero g_cnt.
//   kk = k>>1, klo = k&1, og = o>>2, r = o&3
//   didx = kk*128 + (r>>1)*64 + og*4 + (r&1)*2 + klo
// ---------------------------------------------------------------------------
__global__ void permute_zero_kernel(const float* __restrict__ pre_w,
                                    const float* __restrict__ lin_w, int N) {
    int idx = blockIdx.x * blockDim.x + threadIdx.x;
    if (idx < 448 * 64) {
        int k = idx >> 6;
        int o = idx & 63;
        int seg = k >> 6;
        int ki = k & 63;
        const float* W = (seg < 6) ? (pre_w + seg * 4096) : lin_w;
        float v = W[o * 64 + ki];
        int kk = k >> 1, klo = k & 1;
        int og = o >> 2, r = o & 3;
        int didx = kk * 128 + (r >> 1) * 64 + og * 4 + (r & 1) * 2 + klo;
        g_wt[didx] = v;
    }
    if (idx < N) g_cnt[idx] = 0;
}

// ---------------------------------------------------------------------------
// K1: histogram of destination degrees
// ---------------------------------------------------------------------------
__global__ void count_kernel(const int* __restrict__ erow, int E) {
    int e = blockIdx.x * blockDim.x + threadIdx.x;
    if (e < E) atomicAdd(&g_cnt[erow[e]], 1);
}

// ---------------------------------------------------------------------------
// K2a: per-block exclusive scan of g_cnt -> g_rowptr; block totals -> g_bsum
// ---------------------------------------------------------------------------
__global__ void scan_block_kernel(int n) {
    __shared__ int warp_sums[32];
    int i = blockIdx.x * SCAN_BLK + threadIdx.x;
    int v = (i < n) ? g_cnt[i] : 0;
    int lane = threadIdx.x & 31;
    int wid = threadIdx.x >> 5;

    int s = v;
    #pragma unroll
    for (int o = 1; o < 32; o <<= 1) {
        int t = __shfl_up_sync(0xffffffffu, s, o);
        if (lane >= o) s += t;
    }
    if (lane == 31) warp_sums[wid] = s;
    __syncthreads();
    if (wid == 0) {
        int ws = warp_sums[lane];
        #pragma unroll
        for (int o = 1; o < 32; o <<= 1) {
            int t = __shfl_up_sync(0xffffffffu, ws, o);
            if (lane >= o) ws += t;
        }
        warp_sums[lane] = ws;
    }
    __syncthreads();
    int warp_off = (wid == 0) ? 0 : warp_sums[wid - 1];
    if (i < n) g_rowptr[i] = warp_off + s - v;
    if (threadIdx.x == SCAN_BLK - 1) g_bsum[blockIdx.x] = warp_off + s;
}

// ---------------------------------------------------------------------------
// K2b: parallel exclusive scan of the 98 block sums
// ---------------------------------------------------------------------------
__global__ void scan_top_kernel(int nb) {
    __shared__ int sh[128];
    int t = threadIdx.x;
    int v = (t < nb) ? g_bsum[t] : 0;
    int lane = t & 31, wid = t >> 5;
    int s = v;
    #pragma unroll
    for (int o = 1; o < 32; o <<= 1) {
        int u = __shfl_up_sync(0xffffffffu, s, o);
        if (lane >= o) s += u;
    }
    if (lane == 31) sh[wid] = s;
    __syncthreads();
    if (t == 0) {
        int acc = 0;
        #pragma unroll
        for (int w = 0; w < 4; ++w) { int x = sh[w]; sh[w] = acc; acc += x; }
    }
    __syncthreads();
    if (t < nb) g_bsum[t] = sh[wid] + s - v;
}

// ---------------------------------------------------------------------------
// K2c: add block offsets; init cursors; rowptr[N] = E
// ---------------------------------------------------------------------------
__global__ void scan_add_kernel(int n, int E) {
    int i = blockIdx.x * blockDim.x + threadIdx.x;
    if (i < n) {
        int r = g_rowptr[i] + g_bsum[i >> 10];
        g_rowptr[i] = r;
        g_cur[i] = r;
    }
    if (i == n) g_rowptr[n] = E;
}

// ---------------------------------------------------------------------------
// K3: bucket-scatter edge sources into CSR
// ---------------------------------------------------------------------------
__global__ void scatter_kernel(const int* __restrict__ erow,
                               const int* __restrict__ ecol, int E) {
    int e = blockIdx.x * blockDim.x + threadIdx.x;
    if (e < E) {
        int d = erow[e];
        int pos = atomicAdd(&g_cur[d], 1);
        g_csr[pos] = ecol[e];
    }
}

// ---------------------------------------------------------------------------
// K4: gather-aggregate, 16 lanes/node, unrolled by 2 for MLP.
// ---------------------------------------------------------------------------
__global__ void aggregate_kernel(const float* __restrict__ x, int N) {
    int gid = blockIdx.x * blockDim.x + threadIdx.x;
    int n = gid >> 4;
    if (n >= N) return;
    int lane = gid & 15;

    int beg = g_rowptr[n];
    int end = g_rowptr[n + 1];

    float4 a = make_float4(0.f, 0.f, 0.f, 0.f);
    float4 b = make_float4(0.f, 0.f, 0.f, 0.f);
    const float4* x4 = reinterpret_cast<const float4*>(x);

    int j = beg;
    for (; j + 1 < end; j += 2) {
        int s0 = __ldg(&g_csr[j]);
        int s1 = __ldg(&g_csr[j + 1]);
        float4 v0 = __ldg(&x4[(size_t)s0 * 16 + lane]);
        float4 v1 = __ldg(&x4[(size_t)s1 * 16 + lane]);
        a.x += v0.x; a.y += v0.y; a.z += v0.z; a.w += v0.w;
        b.x += v0.x * v0.x; b.y += v0.y * v0.y;
        b.z += v0.z * v0.z; b.w += v0.w * v0.w;
        a.x += v1.x; a.y += v1.y; a.z += v1.z; a.w += v1.w;
        b.x += v1.x * v1.x; b.y += v1.y * v1.y;
        b.z += v1.z * v1.z; b.w += v1.w * v1.w;
    }
    if (j < end) {
        int s0 = __ldg(&g_csr[j]);
        float4 v0 = __ldg(&x4[(size_t)s0 * 16 + lane]);
        a.x += v0.x; a.y += v0.y; a.z += v0.z; a.w += v0.w;
        b.x += v0.x * v0.x; b.y += v0.y * v0.y;
        b.z += v0.z * v0.z; b.w += v0.w * v0.w;
    }

    size_t off = (size_t)n * 16 + lane;
    reinterpret_cast<float4*>(g_s1)[off] = a;
    reinterpret_cast<float4*>(g_s2)[off] = b;
}

// ---------------------------------------------------------------------------
// K5: finalize GEMM, FFMA2 packed along k.
// 32 nodes/CTA (57 KB smem) -> 2 CTAs/SM: staging (MUFU/loads) of one CTA
// overlaps GEMM (FMA) of the other.
// 256 threads: og = tid&15 (4 outs), ng = tid>>4 (2 nodes).
// ---------------------------------------------------------------------------
__device__ __forceinline__ unsigned long long ffma2(
    unsigned long long a, unsigned long long b, unsigned long long c) {
    unsigned long long d;
    asm("fma.rn.f32x2 %0, %1, %2, %3;" : "=l"(d) : "l"(a), "l"(b), "l"(c));
    return d;
}

__global__ void __launch_bounds__(256, 2)
finalize_kernel(const float* __restrict__ x,
                const float* __restrict__ bias,
                const float* __restrict__ avg_ptr,
                float* __restrict__ out,
                int N) {
    extern __shared__ float Ysh[];                 // [32][448]
    __shared__ float f1s[32], f2s[32];
    const int tid = threadIdx.x;
    const int node0 = blockIdx.x * 32;

    if (tid < 32) {
        int n = node0 + tid;
        float f1 = 0.f, f2 = 0.f;
        if (n < N) {
            float avg = __ldg(avg_ptr);
            float degf = (float)(g_rowptr[n + 1] - g_rowptr[n]);
            float logd = __logf(degf + 1.0f);
            f1 = logd / avg;
            f2 = avg / (logd + EPSV);
        }
        f1s[tid] = f1;
        f2s[tid] = f2;
    }
    __syncthreads();

    // stage augmented features: 32 nodes x 64 dims = 2048 elements
    #pragma unroll
    for (int t = 0; t < 8; ++t) {
        int p = tid + t * 256;
        int nl = p >> 6;
        int i = p & 63;
        int n = node0 + nl;
        float mean = 0.f, stdv = 0.f, xv = 0.f;
        if (n < N) {
            mean = g_s1[(size_t)n * D + i];
            float s2v = g_s2[(size_t)n * D + i];
            float v = fmaxf(s2v - mean * mean, 0.f) + EPSV;
            stdv = v * rsqrtf(v);            // sqrt(v), 1 MUFU + 1 FMUL
            xv = __ldg(x + (size_t)n * D + i);
        }
        float f1 = f1s[nl], f2 = f2s[nl];
        float* Yr = Ysh + nl * 448;
        Yr[i]       = mean;
        Yr[64 + i]  = f1 * mean;
        Yr[128 + i] = f2 * mean;
        Yr[192 + i] = stdv;
        Yr[256 + i] = f1 * stdv;
        Yr[320 + i] = f2 * stdv;
        Yr[384 + i] = xv;
    }
    __syncthreads();

    const int og = tid & 15;          // outs o0..o0+3
    const int ng = tid >> 4;          // nodes na, na+1
    const int o0 = og * 4;
    const int na = ng * 2;

    unsigned long long acc[2][4];
    #pragma unroll
    for (int j = 0; j < 2; ++j)
        #pragma unroll
        for (int q = 0; q < 4; ++q) acc[j][q] = 0ull;

    const ulonglong2* wbase = reinterpret_cast<const ulonglong2*>(g_wt);
    const unsigned long long* Y0 =
        reinterpret_cast<const unsigned long long*>(Ysh + na * 448);
    const unsigned long long* Y1 =
        reinterpret_cast<const unsigned long long*>(Ysh + (na + 1) * 448);

    #pragma unroll 8
    for (int kk = 0; kk < 224; ++kk) {
        ulonglong2 wlo = __ldg(wbase + kk * 32 + og);         // pairs o0, o0+1
        ulonglong2 whi = __ldg(wbase + kk * 32 + 16 + og);    // pairs o0+2, o0+3
        unsigned long long y0 = Y0[kk];
        unsigned long long y1 = Y1[kk];
        acc[0][0] = ffma2(y0, wlo.x, acc[0][0]);
        acc[0][1] = ffma2(y0, wlo.y, acc[0][1]);
        acc[0][2] = ffma2(y0, whi.x, acc[0][2]);
        acc[0][3] = ffma2(y0, whi.y, acc[0][3]);
        acc[1][0] = ffma2(y1, wlo.x, acc[1][0]);
        acc[1][1] = ffma2(y1, wlo.y, acc[1][1]);
        acc[1][2] = ffma2(y1, whi.x, acc[1][2]);
        acc[1][3] = ffma2(y1, whi.y, acc[1][3]);
    }

    float bz[4];
    #pragma unroll
    for (int q = 0; q < 4; ++q) bz[q] = __ldg(bias + o0 + q);

    #pragma unroll
    for (int j = 0; j < 2; ++j) {
        int n = node0 + na + j;
        if (n < N) {
            float4 r;
            float2 p0 = *reinterpret_cast<float2*>(&acc[j][0]);
            float2 p1 = *reinterpret_cast<float2*>(&acc[j][1]);
            float2 p2 = *reinterpret_cast<float2*>(&acc[j][2]);
            float2 p3 = *reinterpret_cast<float2*>(&acc[j][3]);
            r.x = p0.x + p0.y + bz[0];
            r.y = p1.x + p1.y + bz[1];
            r.z = p2.x + p2.y + bz[2];
            r.w = p3.x + p3.y + bz[3];
            *reinterpret_cast<float4*>(out + (size_t)n * D + o0) = r;
        }
    }
}

// ---------------------------------------------------------------------------
// Launch. Inputs: x, edge_row, edge_col, pre_w, lin_w, bias, avg_deg_log
// ---------------------------------------------------------------------------
extern "C" void kernel_launch(void* const* d_in, const int* in_sizes, int n_in,
                              void* d_out, int out_size) {
    const float* x       = (const float*)d_in[0];
    const int*   erow    = (const int*)d_in[1];
    const int*   ecol    = (const int*)d_in[2];
    const float* pre_w   = (const float*)d_in[3];
    const float* lin_w   = (const float*)d_in[4];
    const float* bias    = (const float*)d_in[5];
    const float* avg_log = (const float*)d_in[6];

    const int N = in_sizes[0] / D;
    const int E = in_sizes[1];
    float* out = (float*)d_out;

    permute_zero_kernel<<<(N + 255) / 256, 256>>>(pre_w, lin_w, N);
    count_kernel<<<(E + 255) / 256, 256>>>(erow, E);
    int nsb = (N + SCAN_BLK - 1) / SCAN_BLK;
    scan_block_kernel<<<nsb, SCAN_BLK>>>(N);
    scan_top_kernel<<<1, 128>>>(nsb);
    scan_add_kernel<<<(N + 256) / 256, 256>>>(N, E);
    scatter_kernel<<<(E + 255) / 256, 256>>>(erow, ecol, E);

    {
        long long threads = (long long)N * 16;
        int blocks = (int)((threads + 255) / 256);
        aggregate_kernel<<<blocks, 256>>>(x, N);
    }

    {
        cudaFuncSetAttribute(finalize_kernel,
                             cudaFuncAttributeMaxDynamicSharedMemorySize,
                             32 * 448 * 4);
        int blocks = (N + 31) / 32;
        finalize_kernel<<<blocks, 256, 32 * 448 * 4>>>(
            x, bias, avg_log, out, N);
    }
}